// round 3
// baseline (speedup 1.0000x reference)
#include <cuda_runtime.h>
#include <cuda_bf16.h>
#include <cstdint>

// Problem constants
#define B 16
#define S 4096
#define H 768
#define T 2000

// Scratch: exclusive prefix sums of subtoken_lengths per batch.
__device__ int g_starts[B * T];

// ---------------------------------------------------------------------------
// Kernel 1: per-batch exclusive prefix sum over T lengths.
// One CTA per batch, 1024 threads, 2 elements per thread (int2 loads).
// Shuffle-based scan: 5 shfl (warp) + 5 shfl (cross-warp), 2 barriers.
// ---------------------------------------------------------------------------
__global__ void __launch_bounds__(1024) scan_kernel(const int* __restrict__ lens) {
    const int b    = blockIdx.x;
    const int tid  = threadIdx.x;
    const int lane = tid & 31;
    const int wid  = tid >> 5;

    const int* L = lens + (size_t)b * T;

    // Load 2 adjacent elements per thread (T=2000 is even; tail threads read 0)
    const int idx0 = tid * 2;
    int v0 = 0, v1 = 0;
    if (idx0 + 1 < T) {
        int2 v = *(const int2*)(L + idx0);
        v0 = v.x; v1 = v.y;
    } else if (idx0 < T) {
        v0 = L[idx0];
    }
    int tsum = v0 + v1;

    // Inclusive warp scan of tsum
    int incl = tsum;
#pragma unroll
    for (int off = 1; off < 32; off <<= 1) {
        int n = __shfl_up_sync(0xffffffffu, incl, off);
        if (lane >= off) incl += n;
    }
    const int excl = incl - tsum;

    __shared__ int warpsums[32];
    if (lane == 31) warpsums[wid] = incl;
    __syncthreads();

    if (wid == 0) {
        int w = warpsums[lane];
        int wi = w;
#pragma unroll
        for (int off = 1; off < 32; off <<= 1) {
            int n = __shfl_up_sync(0xffffffffu, wi, off);
            if (lane >= off) wi += n;
        }
        warpsums[lane] = wi - w;   // exclusive
    }
    __syncthreads();

    const int base = warpsums[wid] + excl;
    if (idx0 + 1 < T) {
        *(int2*)(g_starts + (size_t)b * T + idx0) = make_int2(base, base + v0);
    } else if (idx0 < T) {
        g_starts[(size_t)b * T + idx0] = base;
    }
}

// ---------------------------------------------------------------------------
// Kernel 2: one warp per token (grid-stride). Sum len rows (len in {0,1,2}),
// scale by 1/len, write 768 floats. Streaming load/store hints (no reuse).
// ---------------------------------------------------------------------------
__global__ void __launch_bounds__(256) pool_kernel(
    const float* __restrict__ hs,      // [B, S, H]
    const int*   __restrict__ lens,    // [B, T]
    float*       __restrict__ out)     // [B, T, H]
{
    const int lane       = threadIdx.x & 31;
    const int warp0      = (blockIdx.x * blockDim.x + threadIdx.x) >> 5;
    const int totalWarps = (gridDim.x * blockDim.x) >> 5;

    for (int tok = warp0; tok < B * T; tok += totalWarps) {
        const int b     = tok / T;
        const int len   = lens[tok];
        const int start = g_starts[tok];

        float4* dst = (float4*)(out + (size_t)tok * H);

        if (len == 0) {
            const float4 z = make_float4(0.f, 0.f, 0.f, 0.f);
#pragma unroll
            for (int k = 0; k < 6; k++) __stcs(dst + lane + 32 * k, z);
            continue;
        }

        // First covered position is 1 + start (1-based positions)
        const size_t row0 = (size_t)b * S + 1 + start;
        const float4* src0 = (const float4*)(hs + row0 * H);

        float4 acc[6];
#pragma unroll
        for (int k = 0; k < 6; k++) acc[k] = __ldcs(src0 + lane + 32 * k);

        if (len == 2) {
            const float4* src1 = (const float4*)(hs + (row0 + 1) * H);
#pragma unroll
            for (int k = 0; k < 6; k++) {
                float4 v = __ldcs(src1 + lane + 32 * k);
                acc[k].x += v.x; acc[k].y += v.y; acc[k].z += v.z; acc[k].w += v.w;
            }
#pragma unroll
            for (int k = 0; k < 6; k++) {
                acc[k].x *= 0.5f; acc[k].y *= 0.5f; acc[k].z *= 0.5f; acc[k].w *= 0.5f;
            }
        }

#pragma unroll
        for (int k = 0; k < 6; k++) __stcs(dst + lane + 32 * k, acc[k]);
    }
}

// ---------------------------------------------------------------------------
extern "C" void kernel_launch(void* const* d_in, const int* in_sizes, int n_in,
                              void* d_out, int out_size)
{
    const float* hs   = (const float*)d_in[0];   // [B,S,H] fp32
    const int*   lens = (const int*)d_in[1];     // [B,T] int32
    float*       out  = (float*)d_out;           // [B,T,H] fp32

    (void)in_sizes; (void)n_in; (void)out_size;

    scan_kernel<<<B, 1024>>>(lens);

    // Persistent-style grid: 148 SMs * 8 CTAs, 8 warps each -> ~3.4 tokens/warp
    pool_kernel<<<148 * 8, 256>>>(hs, lens, out);
}

// round 4
// speedup vs baseline: 1.0060x; 1.0060x over previous
#include <cuda_runtime.h>
#include <cuda_bf16.h>
#include <cstdint>

// Problem constants
#define B 16
#define S 4096
#define H 768
#define T 2000

#define TOK_PER_CTA 32
#define NCHUNK ((T + TOK_PER_CTA - 1) / TOK_PER_CTA)   // 63

// ---------------------------------------------------------------------------
// Fused kernel: each CTA = one 32-token chunk of one batch.
// Phase 1: block-reduce lens[b][0..t0) -> base; warp0 scans the 32 chunk lens.
// Phase 2: one warp per token (4 tokens/warp), mean-pool len rows (len in 0..2).
// ---------------------------------------------------------------------------
__global__ void __launch_bounds__(256) fused_pool_kernel(
    const float* __restrict__ hs,      // [B, S, H]
    const int*   __restrict__ lens,    // [B, T]
    float*       __restrict__ out)     // [B, T, H]
{
    const int b     = blockIdx.x / NCHUNK;
    const int chunk = blockIdx.x % NCHUNK;
    const int t0    = chunk * TOK_PER_CTA;

    const int tid  = threadIdx.x;
    const int lane = tid & 31;
    const int wid  = tid >> 5;

    const int* L = lens + (size_t)b * T;

    __shared__ int wsum[8];
    __shared__ int s_start[TOK_PER_CTA];
    __shared__ int s_len[TOK_PER_CTA];

    // ---- Phase 1a: partial sums of lens[b][0..t0) ----
    int part = 0;
    for (int i = tid; i < t0; i += 256) part += L[i];
#pragma unroll
    for (int off = 16; off > 0; off >>= 1)
        part += __shfl_down_sync(0xffffffffu, part, off);
    if (lane == 0) wsum[wid] = part;
    __syncthreads();

    // ---- Phase 1b: warp 0 finishes base + scans the chunk's 32 lens ----
    if (wid == 0) {
        int v = (lane < 8) ? wsum[lane] : 0;
        v += __shfl_xor_sync(0xffffffffu, v, 4);
        v += __shfl_xor_sync(0xffffffffu, v, 2);
        v += __shfl_xor_sync(0xffffffffu, v, 1);
        const int base = __shfl_sync(0xffffffffu, v, 0);

        const int tok = t0 + lane;
        const int len = (tok < T) ? L[tok] : 0;
        int incl = len;
#pragma unroll
        for (int off = 1; off < 32; off <<= 1) {
            int n = __shfl_up_sync(0xffffffffu, incl, off);
            if (lane >= off) incl += n;
        }
        s_start[lane] = base + incl - len;   // exclusive prefix
        s_len[lane]   = len;
    }
    __syncthreads();

    // ---- Phase 2: pool. warp w handles chunk tokens w, w+8, w+16, w+24 ----
#pragma unroll
    for (int i = wid; i < TOK_PER_CTA; i += 8) {
        const int tok = t0 + i;
        if (tok >= T) break;

        const int len   = s_len[i];
        const int start = s_start[i];

        float4* dst = (float4*)(out + ((size_t)b * T + tok) * H);

        if (len == 0) {
            const float4 z = make_float4(0.f, 0.f, 0.f, 0.f);
#pragma unroll
            for (int k = 0; k < 6; k++) dst[lane + 32 * k] = z;
            continue;
        }

        // First covered position is 1 + start (1-based positions)
        const size_t row0 = (size_t)b * S + 1 + start;
        const float4* src0 = (const float4*)(hs + row0 * H);

        float4 acc[6];
#pragma unroll
        for (int k = 0; k < 6; k++) acc[k] = src0[lane + 32 * k];

        if (len == 2) {
            const float4* src1 = (const float4*)(hs + (row0 + 1) * H);
#pragma unroll
            for (int k = 0; k < 6; k++) {
                float4 v = src1[lane + 32 * k];
                acc[k].x += v.x; acc[k].y += v.y; acc[k].z += v.z; acc[k].w += v.w;
            }
#pragma unroll
            for (int k = 0; k < 6; k++) {
                acc[k].x *= 0.5f; acc[k].y *= 0.5f; acc[k].z *= 0.5f; acc[k].w *= 0.5f;
            }
        }

#pragma unroll
        for (int k = 0; k < 6; k++) dst[lane + 32 * k] = acc[k];
    }
}

// ---------------------------------------------------------------------------
extern "C" void kernel_launch(void* const* d_in, const int* in_sizes, int n_in,
                              void* d_out, int out_size)
{
    const float* hs   = (const float*)d_in[0];   // [B,S,H] fp32
    const int*   lens = (const int*)d_in[1];     // [B,T] int32
    float*       out  = (float*)d_out;           // [B,T,H] fp32

    (void)in_sizes; (void)n_in; (void)out_size;

    fused_pool_kernel<<<B * NCHUNK, 256>>>(hs, lens, out);
}